// round 9
// baseline (speedup 1.0000x reference)
#include <cuda_runtime.h>
#include <cstdint>

// Problem: B=8, L=256, Z=16, H=256
// Reassociated contraction order (12.9 GFLOP total):
//   A: Wc[bz][i][j] = sum_o cls[bz][o] * W[i][o][j]   -> tf32 mma.sync (3-term split)
//   B: t[b][x][z][j] = sum_i start[b][x][i] * Wc[bz][i][j]   (SIMT FFMA2, R7)
//   C: out[b][x][y][z] = sum_j t[b][x][z][j] * end[b][y][j]  (SIMT FFMA2, R7)

__device__ float g_wc[8388608];   // [bz=128][i=256][j=256] fp32
__device__ float g_t [8388608];   // [b=8][x=256][z=16][j=256] fp32
__device__ unsigned g_clsh[32768]; // cls tf32-hi bit patterns [bz=128][o=256]
__device__ unsigned g_clsl[32768]; // cls tf32-lo

#define TILE 128
#define KT   8
#define NSTAGE 32

typedef unsigned long long u64;

// ---------------- tf32 helpers -------------------------------------------
__device__ __forceinline__ unsigned f2tf32(float f) {
    unsigned u;
    asm("cvt.rna.tf32.f32 %0, %1;" : "=r"(u) : "f"(f));
    return u;
}
// mma.sync m16n8k8 tf32: D(16x8,f32) += A(16x8) * B(8x8)
__device__ __forceinline__ void mma_tf32(float d[4], unsigned a0, unsigned a1,
                                         unsigned a2, unsigned a3,
                                         unsigned b0, unsigned b1)
{
    asm volatile(
        "mma.sync.aligned.m16n8k8.row.col.f32.tf32.tf32.f32 "
        "{%0,%1,%2,%3}, {%4,%5,%6,%7}, {%8,%9}, {%0,%1,%2,%3};"
        : "+f"(d[0]), "+f"(d[1]), "+f"(d[2]), "+f"(d[3])
        : "r"(a0), "r"(a1), "r"(a2), "r"(a3), "r"(b0), "r"(b1));
}

// ---------------- stage-A split pre-pass (cls only; W split in-kernel) ----
__global__ void split_cls(const float* __restrict__ cls)
{
    int idx = blockIdx.x * 256 + threadIdx.x;   // 0..32767
    float f = cls[idx];
    unsigned hu = f2tf32(f);
    float lo = f - __uint_as_float(hu);
    g_clsh[idx] = hu;
    g_clsl[idx] = f2tf32(lo);
}

// ---------------------------------------------------------------------------
// Stage A: per (j-half, i) CTA computes Wc[bz=128][j=128] over K=o=256.
// 256 threads = 8 warps (4m x 2n), warp tile 32(m) x 64(n).
// smem: As[hi/lo][k=8][m pad 136], Ws[hi/lo][k=8][n pad 264] (u32 tf32 bits)
// Fragment bank math: LDS addr mod 32 = k*8 + m(or n) -> all lanes distinct.
// ---------------------------------------------------------------------------
#define APAD 136
#define BPAD 264

__global__ __launch_bounds__(256, 2)
void kernA_mma(const float* __restrict__ W)
{
    __shared__ unsigned AsH[8][APAD], AsL[8][APAD];
    __shared__ unsigned WsH[8][BPAD], WsL[8][BPAD];

    int tid  = threadIdx.x;
    int lane = tid & 31;
    int wid  = tid >> 5;
    int j0   = blockIdx.x * 128;
    int i_dim = blockIdx.z;

    int wm = (wid & 3) * 32;     // warp m offset (bz)
    int wn = (wid >> 2) * 64;    // warp n offset (j within 128)

    const float* Wi = W + (long)i_dim * 65536;   // [o=256][j=256]

    float acc[2][8][4];
#pragma unroll
    for (int mb = 0; mb < 2; mb++)
#pragma unroll
        for (int nb = 0; nb < 8; nb++)
#pragma unroll
            for (int q = 0; q < 4; q++) acc[mb][nb][q] = 0.f;

    // per-thread load roles
    int wrow = tid >> 5;           // 0..7 : W chunk row (= k within chunk)
    int wcol = (tid & 31) * 8;     // 0..248 : 8 floats (2 float4)
    int cm  = tid >> 1;            // 0..127 : cls m row
    int ckq = (tid & 1) * 4;       // cls k quarter offset (0 or 4)

    for (int c = 0; c < 32; c++) {          // 32 chunks of k=8
        int k0 = c * 8;

        // load W chunk [8 o][256 j] fp32 -> split -> WsH/WsL[k][j0..j0+127]
        // (only our 128-j half)
        {
            // 8 rows x 128 cols of our half = 1024 floats; 256 thr x 4
            int rr = tid >> 5;                 // row 0..7
            int cc = (tid & 31) * 4;           // col 0..124
            float4 v = *(const float4*)(Wi + (long)(k0 + rr) * 256 + j0 + cc);
            float fs[4] = {v.x, v.y, v.z, v.w};
#pragma unroll
            for (int e = 0; e < 4; e++) {
                unsigned hu = f2tf32(fs[e]);
                float lo = fs[e] - __uint_as_float(hu);
                WsH[rr][cc + e] = hu;
                WsL[rr][cc + e] = f2tf32(lo);
            }
        }
        // load cls chunk [128 m][8 k] (pre-split) -> AsH/AsL[k][m]
        {
            const unsigned* ch = g_clsh + (long)cm * 256 + k0 + ckq;
            const unsigned* cl = g_clsl + (long)cm * 256 + k0 + ckq;
            uint4 vh = *(const uint4*)ch;
            uint4 vl = *(const uint4*)cl;
            AsH[ckq + 0][cm] = vh.x; AsH[ckq + 1][cm] = vh.y;
            AsH[ckq + 2][cm] = vh.z; AsH[ckq + 3][cm] = vh.w;
            AsL[ckq + 0][cm] = vl.x; AsL[ckq + 1][cm] = vl.y;
            AsL[ckq + 2][cm] = vl.z; AsL[ckq + 3][cm] = vl.w;
        }
        __syncthreads();

        // fragments: A a0:(r,k) a1:(r+8,k) a2:(r,k+4) a3:(r+8,k+4); r=lane/4,k=lane%4
        int fr = lane >> 2;      // 0..7
        int fk = lane & 3;       // 0..3
        unsigned ah[2][4], al[2][4];
#pragma unroll
        for (int mb = 0; mb < 2; mb++) {
            int m = wm + mb * 16 + fr;
            ah[mb][0] = AsH[fk][m];     ah[mb][1] = AsH[fk][m + 8];
            ah[mb][2] = AsH[fk + 4][m]; ah[mb][3] = AsH[fk + 4][m + 8];
            al[mb][0] = AsL[fk][m];     al[mb][1] = AsL[fk][m + 8];
            al[mb][2] = AsL[fk + 4][m]; al[mb][3] = AsL[fk + 4][m + 8];
        }
#pragma unroll
        for (int nb = 0; nb < 8; nb++) {
            // B b0:(k=lane%4, n=lane/4), b1:(k+4, n)
            int n = wn + nb * 8 + fr;
            unsigned bh0 = WsH[fk][n],     bh1 = WsH[fk + 4][n];
            unsigned bl0 = WsL[fk][n],     bl1 = WsL[fk + 4][n];
#pragma unroll
            for (int mb = 0; mb < 2; mb++) {
                mma_tf32(acc[mb][nb], ah[mb][0], ah[mb][1], ah[mb][2], ah[mb][3], bh0, bh1); // hi*hi
                mma_tf32(acc[mb][nb], ah[mb][0], ah[mb][1], ah[mb][2], ah[mb][3], bl0, bl1); // hi*lo
                mma_tf32(acc[mb][nb], al[mb][0], al[mb][1], al[mb][2], al[mb][3], bh0, bh1); // lo*hi
            }
        }
        __syncthreads();
    }

    // epilogue: D element mapping c0:(r,2c) c1:(r,2c+1) c2:(r+8,2c) c3:(r+8,2c+1)
    int fr = lane >> 2, fc = (lane & 3) * 2;
#pragma unroll
    for (int mb = 0; mb < 2; mb++) {
#pragma unroll
        for (int nb = 0; nb < 8; nb++) {
            long m = wm + mb * 16 + fr;          // bz row
            long j = j0 + wn + nb * 8 + fc;      // j col
            float* p0 = g_wc + m * 65536 + (long)i_dim * 256 + j;
            float* p1 = p0 + 8 * 65536;          // row m+8
            p0[0] = acc[mb][nb][0]; p0[1] = acc[mb][nb][1];
            p1[0] = acc[mb][nb][2]; p1[1] = acc[mb][nb][3];
        }
    }
}

// ===================== SIMT FFMA2 machinery (stages B, C — R7 best) =========
__device__ __forceinline__ u64 dupf(float v) {
    u64 r; unsigned u = __float_as_uint(v);
    asm("mov.b64 %0, {%1, %1};" : "=l"(r) : "r"(u));
    return r;
}
__device__ __forceinline__ void fma2(u64& d, u64 a, u64 b) {
    asm("fma.rn.f32x2 %0, %1, %2, %0;" : "+l"(d) : "l"(a), "l"(b));
}
__device__ __forceinline__ void unpk(u64 v, float& lo, float& hi) {
    unsigned l, h;
    asm("mov.b64 {%0, %1}, %2;" : "=r"(l), "=r"(h) : "l"(v));
    lo = __uint_as_float(l); hi = __uint_as_float(h);
}

__device__ __forceinline__ void mk_compute(const float (*As)[TILE], const float (*Bs)[TILE],
                                           int tx, int ty, u64 acc[4][8])
{
#pragma unroll
    for (int kk = 0; kk < KT; kk++) {
        ulonglong2 a01 = *(const ulonglong2*)&As[kk][ty * 8];
        ulonglong2 a23 = *(const ulonglong2*)&As[kk][ty * 8 + 4];
        u64 ap[4]; ap[0] = a01.x; ap[1] = a01.y; ap[2] = a23.x; ap[3] = a23.y;

        float4 b0 = *(const float4*)&Bs[kk][tx * 4];
        float4 b1 = *(const float4*)&Bs[kk][64 + tx * 4];
        u64 bd[8];
        bd[0] = dupf(b0.x); bd[1] = dupf(b0.y); bd[2] = dupf(b0.z); bd[3] = dupf(b0.w);
        bd[4] = dupf(b1.x); bd[5] = dupf(b1.y); bd[6] = dupf(b1.z); bd[7] = dupf(b1.w);
#pragma unroll
        for (int ip = 0; ip < 4; ip++)
#pragma unroll
            for (int j = 0; j < 8; j++)
                fma2(acc[ip][j], ap[ip], bd[j]);
    }
}

__device__ __forceinline__ void mk_unpack(u64 acc[4][8], float c[8][8])
{
#pragma unroll
    for (int ip = 0; ip < 4; ip++)
#pragma unroll
        for (int j = 0; j < 8; j++)
            unpk(acc[ip][j], c[2 * ip][j], c[2 * ip + 1][j]);
}

// Kernel B: per bz, NN GEMM 256x256x256: t[b][x][z][j] = start[b][x][:] @ Wc[bz]
__global__ __launch_bounds__(256, 2)
void kernB(const float* __restrict__ start)
{
    int bz = blockIdx.z;
    int b = bz >> 4, z = bz & 15;
    const float* A  = start + (long)b * 65536;
    const float* Bm = g_wc  + (long)bz * 65536;
    float* C = g_t + (long)b * 1048576 + (long)z * 256;

    __shared__ float As[2][KT][TILE];
    __shared__ float Bs[2][KT][TILE];

    int tid = threadIdx.x;
    int tx = tid & 15, ty = tid >> 4;
    int m0 = blockIdx.y * TILE;
    int n0 = blockIdx.x * TILE;

    int lr = tid >> 1, lc = (tid & 1) * 4;
    int bk = tid >> 5, bn = (tid & 31) * 4;

    u64 acc[4][8];
#pragma unroll
    for (int ip = 0; ip < 4; ip++)
#pragma unroll
        for (int j = 0; j < 8; j++) acc[ip][j] = 0ULL;

    {
        float4 av = *(const float4*)(A + (long)(m0 + lr) * 256 + lc);
        As[0][lc + 0][lr] = av.x; As[0][lc + 1][lr] = av.y;
        As[0][lc + 2][lr] = av.z; As[0][lc + 3][lr] = av.w;
        *(float4*)&Bs[0][bk][bn] = *(const float4*)(Bm + (long)bk * 256 + n0 + bn);
    }
    __syncthreads();

    int buf = 0;
#pragma unroll 2
    for (int s = 0; s < NSTAGE; s++) {
        float4 nav, nbv;
        if (s + 1 < NSTAGE) {
            int k1 = (s + 1) * KT;
            nav = *(const float4*)(A + (long)(m0 + lr) * 256 + k1 + lc);
            nbv = *(const float4*)(Bm + (long)(k1 + bk) * 256 + n0 + bn);
        }
        mk_compute(As[buf], Bs[buf], tx, ty, acc);
        if (s + 1 < NSTAGE) {
            int nb = buf ^ 1;
            As[nb][lc + 0][lr] = nav.x; As[nb][lc + 1][lr] = nav.y;
            As[nb][lc + 2][lr] = nav.z; As[nb][lc + 3][lr] = nav.w;
            *(float4*)&Bs[nb][bk][bn] = nbv;
            __syncthreads();
            buf = nb;
        }
    }

    float c[8][8];
    mk_unpack(acc, c);
#pragma unroll
    for (int i = 0; i < 8; i++) {
        long x = m0 + ty * 8 + i;
        float* base = C + x * 4096 + n0;
        *(float4*)(base + tx * 4)      = make_float4(c[i][0], c[i][1], c[i][2], c[i][3]);
        *(float4*)(base + 64 + tx * 4) = make_float4(c[i][4], c[i][5], c[i][6], c[i][7]);
    }
}

// Kernel C: per b, NT GEMM M=4096 (m=x*16+z), N=256 (y), K=256 (j)
__global__ __launch_bounds__(256, 2)
void kernC(const float* __restrict__ endl, float* __restrict__ out)
{
    int b = blockIdx.z;
    const float* A  = g_t  + (long)b * 1048576;
    const float* Bm = endl + (long)b * 65536;
    float* O = out + (long)b * 1048576;

    __shared__ float As[2][KT][TILE];
    __shared__ float Bs[2][KT][TILE];

    int tid = threadIdx.x;
    int tx = tid & 15, ty = tid >> 4;
    int m0 = blockIdx.y * TILE;
    int n0 = blockIdx.x * TILE;

    int lr = tid >> 1, lc = (tid & 1) * 4;

    u64 acc[4][8];
#pragma unroll
    for (int ip = 0; ip < 4; ip++)
#pragma unroll
        for (int j = 0; j < 8; j++) acc[ip][j] = 0ULL;

    {
        float4 av = *(const float4*)(A + (long)(m0 + lr) * 256 + lc);
        As[0][lc + 0][lr] = av.x; As[0][lc + 1][lr] = av.y;
        As[0][lc + 2][lr] = av.z; As[0][lc + 3][lr] = av.w;
        float4 bv = *(const float4*)(Bm + (long)(n0 + lr) * 256 + lc);
        Bs[0][lc + 0][lr] = bv.x; Bs[0][lc + 1][lr] = bv.y;
        Bs[0][lc + 2][lr] = bv.z; Bs[0][lc + 3][lr] = bv.w;
    }
    __syncthreads();

    int buf = 0;
#pragma unroll 2
    for (int s = 0; s < NSTAGE; s++) {
        float4 nav, nbv;
        if (s + 1 < NSTAGE) {
            int k1 = (s + 1) * KT;
            nav = *(const float4*)(A + (long)(m0 + lr) * 256 + k1 + lc);
            nbv = *(const float4*)(Bm + (long)(n0 + lr) * 256 + k1 + lc);
        }
        mk_compute(As[buf], Bs[buf], tx, ty, acc);
        if (s + 1 < NSTAGE) {
            int nb = buf ^ 1;
            As[nb][lc + 0][lr] = nav.x; As[nb][lc + 1][lr] = nav.y;
            As[nb][lc + 2][lr] = nav.z; As[nb][lc + 3][lr] = nav.w;
            Bs[nb][lc + 0][lr] = nbv.x; Bs[nb][lc + 1][lr] = nbv.y;
            Bs[nb][lc + 2][lr] = nbv.z; Bs[nb][lc + 3][lr] = nbv.w;
            __syncthreads();
            buf = nb;
        }
    }

    float c[8][8];
    mk_unpack(acc, c);

    int m = m0 + ty * 8;
    long x  = m >> 4;
    int  z0 = m & 15;
#pragma unroll
    for (int j = 0; j < 8; j++) {
        long y = n0 + (j < 4 ? (tx * 4 + j) : (64 + tx * 4 + j - 4));
        float* p = O + x * 4096 + y * 16 + z0;
        *(float4*)(p)     = make_float4(c[0][j], c[1][j], c[2][j], c[3][j]);
        *(float4*)(p + 4) = make_float4(c[4][j], c[5][j], c[6][j], c[7][j]);
    }
}

// ===================== launch ================================================
extern "C" void kernel_launch(void* const* d_in, const int* in_sizes, int n_in,
                              void* d_out, int out_size)
{
    const float* start = (const float*)d_in[0];   // [8,256,256]
    const float* endl  = (const float*)d_in[1];   // [8,256,256]
    const float* cls   = (const float*)d_in[2];   // [8,16,256]
    const float* W     = (const float*)d_in[3];   // [256,256,256]
    float* out = (float*)d_out;                   // [8,256,256,16]

    split_cls<<<128, 256>>>(cls);

    dim3 gA(2, 1, 256);      // j-half, -, i
    kernA_mma<<<gA, 256>>>(W);

    dim3 gB(2, 2, 128);      // j, x, bz
    kernB<<<gB, 256>>>(start);

    dim3 gC(2, 32, 8);       // y, m, b
    kernC<<<gC, 256>>>(endl, out);
}